// round 10
// baseline (speedup 1.0000x reference)
#include <cuda_runtime.h>
#include <cuda_bf16.h>
#include <cstdint>
#include <cstddef>

#define T_SEQ   2048
#define C_EMB   1024
#define HDIM    16
#define NHEADS  64

// Scratch (no cudaMalloc allowed)
__device__ float g_qkv[T_SEQ * 3 * C_EMB];          // Q/K channels k-permuted, V natural
__device__ float g_attn[T_SEQ * C_EMB];             // channels k-permuted
__device__ float g_x[T_SEQ * C_EMB];                // k-permuted
__device__ float g_wqkv[3 * C_EMB * C_EMB];         // transposed [3072][1024], k-permuted
__device__ float g_wout[C_EMB * C_EMB];             // transposed [1024][1024], k-permuted
__device__ __nv_bfloat16 g_vth[NHEADS * HDIM * T_SEQ];
__device__ __nv_bfloat16 g_vtl[NHEADS * HDIM * T_SEQ];

// within-8 k-permutation: logical p -> storage sperm(p); storage order = {0,4,1,5,2,6,3,7}
__device__ __host__ __forceinline__ int sperm(int p) { return ((p & 3) << 1) | (p >> 2); }

__device__ __forceinline__ uint32_t f2tf32(float x) {
    uint32_t u;
    asm("cvt.rna.tf32.f32 %0, %1;" : "=r"(u) : "f"(x));
    return u;
}
__device__ __forceinline__ float u2f(uint32_t u) { return __uint_as_float(u); }

__device__ __forceinline__ uint32_t pack_bf16x2(float lo, float hi) {
    uint32_t d;
    asm("cvt.rn.bf16x2.f32 %0, %1, %2;" : "=r"(d) : "f"(hi), "f"(lo));
    return d;
}

__device__ __forceinline__ void mma_tf32(float c[4], const uint32_t a[4],
                                         uint32_t b0, uint32_t b1) {
    asm volatile(
        "mma.sync.aligned.m16n8k8.row.col.f32.tf32.tf32.f32 "
        "{%0,%1,%2,%3}, {%4,%5,%6,%7}, {%8,%9}, {%0,%1,%2,%3};"
        : "+f"(c[0]), "+f"(c[1]), "+f"(c[2]), "+f"(c[3])
        : "r"(a[0]), "r"(a[1]), "r"(a[2]), "r"(a[3]), "r"(b0), "r"(b1));
}

__device__ __forceinline__ void mma_bf16(float c[4], const uint32_t a[4],
                                         uint32_t b0, uint32_t b1) {
    asm volatile(
        "mma.sync.aligned.m16n8k16.row.col.f32.bf16.bf16.f32 "
        "{%0,%1,%2,%3}, {%4,%5,%6,%7}, {%8,%9}, {%0,%1,%2,%3};"
        : "+f"(c[0]), "+f"(c[1]), "+f"(c[2]), "+f"(c[3])
        : "r"(a[0]), "r"(a[1]), "r"(a[2]), "r"(a[3]), "r"(b0), "r"(b1));
}

#define CP_ASYNC16(dst, src) \
    asm volatile("cp.async.cg.shared.global [%0], [%1], 16;" :: "r"(dst), "l"(src))
#define CP_COMMIT() asm volatile("cp.async.commit_group;")
#define CP_WAIT(n)  asm volatile("cp.async.wait_group %0;" :: "n"(n))

// ---------------------------------------------------------------------------
// Prologue: tf32 round + within-8 k-permutation (gather form).
// storage q holds logical {0,4,1,5,2,6,3,7}[q].
// ---------------------------------------------------------------------------
__global__ void cvt_perm_kernel(const float* __restrict__ in,
                                float* __restrict__ out, int n8)
{
    int i = blockIdx.x * blockDim.x + threadIdx.x;
    if (i >= n8) return;
    float4 va = ((const float4*)in)[2 * i];
    float4 vb = ((const float4*)in)[2 * i + 1];
    float4 o1, o2;
    o1.x = u2f(f2tf32(va.x)); o1.y = u2f(f2tf32(vb.x));   // logical 0,4
    o1.z = u2f(f2tf32(va.y)); o1.w = u2f(f2tf32(vb.y));   // logical 1,5
    o2.x = u2f(f2tf32(va.z)); o2.y = u2f(f2tf32(vb.z));   // logical 2,6
    o2.z = u2f(f2tf32(va.w)); o2.w = u2f(f2tf32(vb.w));   // logical 3,7
    ((float4*)out)[2 * i]     = o1;
    ((float4*)out)[2 * i + 1] = o2;
}

// Prologue: out[n][kperm] = tf32(in[k][n]);  in is [R x Ccols], R = K dim.
__global__ void transpose_cvt_perm_kernel(const float* __restrict__ in,
                                          float* __restrict__ out, int R, int Ccols)
{
    __shared__ float t[32][33];
    const int bx = blockIdx.x * 32;   // n tile
    const int by = blockIdx.y * 32;   // k tile
    const int tx = threadIdx.x, ty = threadIdx.y;   // 32 x 8
#pragma unroll
    for (int j = 0; j < 4; j++) {
        int r = by + ty + j * 8;
        t[ty + j * 8][tx] = u2f(f2tf32(in[(size_t)r * Ccols + bx + tx]));
    }
    __syncthreads();
    const int kperm = by + (tx & ~7) + sperm(tx & 7);
#pragma unroll
    for (int j = 0; j < 4; j++) {
        int n = bx + ty + j * 8;
        out[(size_t)n * R + kperm] = t[tx][ty + j * 8];
    }
}

// ---------------------------------------------------------------------------
// V transpose to hi/lo bf16 (V channels natural; token dim is PV's k).
// ---------------------------------------------------------------------------
__global__ void vt_kernel(const float* __restrict__ qkv,
                          __nv_bfloat16* __restrict__ vth,
                          __nv_bfloat16* __restrict__ vtl)
{
    __shared__ __nv_bfloat16 smh[16][132];
    __shared__ __nv_bfloat16 sml[16][132];
    const int h   = blockIdx.x;
    const int tt  = blockIdx.y;
    const int tid = threadIdx.x;
    const int token = tt * 128 + tid;

    const float* vp = qkv + (size_t)token * (3 * C_EMB) + 2 * C_EMB + h * HDIM;
#pragma unroll
    for (int c = 0; c < 16; c++) {
        float v = vp[c];
        __nv_bfloat16 hb = __float2bfloat16(v);
        float lo = v - __bfloat162float(hb);
        smh[c][tid] = hb;
        sml[c][tid] = __float2bfloat16(lo);
    }
    __syncthreads();

    const int d  = tid >> 3;
    const int c0 = (tid & 7) * 16;
    size_t base = ((size_t)(h * HDIM + d)) * T_SEQ + tt * 128 + c0;
    uint32_t* oh = (uint32_t*)(vth + base);
    uint32_t* ol = (uint32_t*)(vtl + base);
#pragma unroll
    for (int i = 0; i < 8; i++) {
        oh[i] = *(const uint32_t*)&smh[d][c0 + 2 * i];
        ol[i] = *(const uint32_t*)&sml[d][c0 + 2 * i];
    }
}

// ---------------------------------------------------------------------------
// TF32 GEMM, k-permuted operands: C[M,N] = A[M,K] @ Bt[N,K]^T + bias[N].
// Both A and Bt are [row][k] with within-8 k-permutation -> every fragment
// is one float2 LDS (stride 24 => conflict-free). 128x128 CTA, BK=16,
// 4 warps (64x64 tiles), 2-stage cp.async, one barrier per iter.
// PERM_QK: permute output columns < 2048 (Q/K ranges) within-8.
// ---------------------------------------------------------------------------
template <bool ROUND_OUT, bool PERM_QK>
__global__ __launch_bounds__(128, 2) void gemm_tf32_bias_kernel(
    const float* __restrict__ A, const float* __restrict__ Bt,
    const float* __restrict__ bias, float* __restrict__ C,
    int M, int N, int K)
{
    __shared__ __align__(16) float As[2][128][24];
    __shared__ __align__(16) float Bs[2][128][24];

    const int tid  = threadIdx.x;
    const int lane = tid & 31;
    const int warp = tid >> 5;
    const int wm   = (warp >> 1) * 64;
    const int wn   = (warp & 1) * 64;
    const int g    = lane >> 2;
    const int t4   = lane & 3;
    const int row0 = blockIdx.y * 128;
    const int col0 = blockIdx.x * 128;

    float acc[4][8][4];
#pragma unroll
    for (int ms = 0; ms < 4; ms++)
#pragma unroll
        for (int ns = 0; ns < 8; ns++)
#pragma unroll
            for (int i = 0; i < 4; i++) acc[ms][ns][i] = 0.f;

    auto issue_loads = [&](int k0, int st) {
#pragma unroll
        for (int it = 0; it < 4; it++) {
            int lin = tid + it * 128;           // 0..511
            int r   = lin >> 2;                 // 0..127
            int kc  = (lin & 3) * 4;
            CP_ASYNC16((uint32_t)__cvta_generic_to_shared(&As[st][r][kc]),
                       A + (size_t)(row0 + r) * K + k0 + kc);
            CP_ASYNC16((uint32_t)__cvta_generic_to_shared(&Bs[st][r][kc]),
                       Bt + (size_t)(col0 + r) * K + k0 + kc);
        }
    };

    const int niter = K / 16;
    issue_loads(0, 0);
    CP_COMMIT();

    for (int i = 0; i < niter; i++) {
        CP_WAIT(0);
        __syncthreads();
        if (i + 1 < niter) {
            issue_loads((i + 1) * 16, (i + 1) & 1);
            CP_COMMIT();
        }
        const int st = i & 1;
#pragma unroll
        for (int kk = 0; kk < 16; kk += 8) {
            uint32_t af[4][4];
#pragma unroll
            for (int ms = 0; ms < 4; ms++) {
                float2 p0 = *(const float2*)&As[st][wm + ms * 16 + g    ][kk + 2 * t4];
                float2 p1 = *(const float2*)&As[st][wm + ms * 16 + g + 8][kk + 2 * t4];
                af[ms][0] = __float_as_uint(p0.x);   // (g,   t4)
                af[ms][1] = __float_as_uint(p1.x);   // (g+8, t4)
                af[ms][2] = __float_as_uint(p0.y);   // (g,   t4+4)
                af[ms][3] = __float_as_uint(p1.y);   // (g+8, t4+4)
            }
            uint32_t bf[8][2];
#pragma unroll
            for (int ns = 0; ns < 8; ns++) {
                float2 pb = *(const float2*)&Bs[st][wn + ns * 8 + g][kk + 2 * t4];
                bf[ns][0] = __float_as_uint(pb.x);
                bf[ns][1] = __float_as_uint(pb.y);
            }
#pragma unroll
            for (int ms = 0; ms < 4; ms++)
#pragma unroll
                for (int ns = 0; ns < 8; ns++)
                    mma_tf32(acc[ms][ns], af[ms], bf[ns][0], bf[ns][1]);
        }
    }

    const bool perm_out = PERM_QK && (col0 < 2048);
    const int sp0 = sperm(2 * t4);
    const int sp1 = sperm(2 * t4 + 1);
#pragma unroll
    for (int ms = 0; ms < 4; ms++) {
#pragma unroll
        for (int ns = 0; ns < 8; ns++) {
            int r  = row0 + wm + ms * 16 + g;
            int cb = col0 + wn + ns * 8;
            float2 bv = *(const float2*)(bias + cb + 2 * t4);   // logical channels
            float2 o0, o1;
            o0.x = acc[ms][ns][0] + bv.x; o0.y = acc[ms][ns][1] + bv.y;
            o1.x = acc[ms][ns][2] + bv.x; o1.y = acc[ms][ns][3] + bv.y;
            if (ROUND_OUT) {
                o0.x = u2f(f2tf32(o0.x)); o0.y = u2f(f2tf32(o0.y));
                o1.x = u2f(f2tf32(o1.x)); o1.y = u2f(f2tf32(o1.y));
            }
            if (perm_out) {
                C[(size_t)r * N + cb + sp0]       = o0.x;
                C[(size_t)r * N + cb + sp1]       = o0.y;
                C[(size_t)(r + 8) * N + cb + sp0] = o1.x;
                C[(size_t)(r + 8) * N + cb + sp1] = o1.y;
            } else {
                *(float2*)(C + (size_t)r * N + cb + 2 * t4)       = o0;
                *(float2*)(C + (size_t)(r + 8) * N + cb + 2 * t4) = o1;
            }
        }
    }
}

// ---------------------------------------------------------------------------
// Flash attention (causal): scores tf32 (Q/K channels k-permuted -> 64-bit
// fragment loads), PV bf16 hi/lo. Output channels stored k-permuted for the
// projection GEMM. Block: 1 head x 64 q-rows, 4 warps, 64-key chunks.
// ---------------------------------------------------------------------------
__global__ __launch_bounds__(128) void attn_tc_kernel(
    const float* __restrict__ qkv,
    const __nv_bfloat16* __restrict__ vth,
    const __nv_bfloat16* __restrict__ vtl,
    float* __restrict__ attn_out)
{
    __shared__ __align__(16) float Ks[2][64][24];
    __shared__ __align__(16) __nv_bfloat16 Vh[2][16][72];
    __shared__ __align__(16) __nv_bfloat16 Vl[2][16][72];

    const unsigned F = 0xffffffffu;
    const int h    = blockIdx.y;
    const int qt   = (int)gridDim.x - 1 - (int)blockIdx.x;  // heavy tiles first
    const int tid  = threadIdx.x;
    const int lane = tid & 31;
    const int w    = tid >> 5;
    const int g    = lane >> 2;
    const int t4   = lane & 3;
    const int qbase = qt * 64 + w * 16;

    const int krow = tid >> 1;
    const int kcol = (tid & 1) * 8;
    const int vdim = tid >> 3;
    const int vseg = (tid & 7) * 8;

    auto prefetch = [&](int ci) {
        const int st = ci & 1;
        const float* kp = qkv + (size_t)(ci * 64 + krow) * (3 * C_EMB)
                          + C_EMB + h * HDIM + kcol;
        CP_ASYNC16((uint32_t)__cvta_generic_to_shared(&Ks[st][krow][kcol    ]), kp);
        CP_ASYNC16((uint32_t)__cvta_generic_to_shared(&Ks[st][krow][kcol + 4]), kp + 4);
        size_t vbase = (size_t)(h * HDIM + vdim) * T_SEQ + ci * 64 + vseg;
        CP_ASYNC16((uint32_t)__cvta_generic_to_shared(&Vh[st][vdim][vseg]), vth + vbase);
        CP_ASYNC16((uint32_t)__cvta_generic_to_shared(&Vl[st][vdim][vseg]), vtl + vbase);
    };

    // Q fragments (x0.25 exact): channels permuted -> float2 gives (t4, t4+4)
    uint32_t qa[2][4];
    {
        const float* qp = qkv + (size_t)qbase * (3 * C_EMB) + h * HDIM;
#pragma unroll
        for (int kt = 0; kt < 2; kt++) {
            float2 a02 = *(const float2*)(qp + (size_t)g       * (3 * C_EMB) + kt * 8 + 2 * t4);
            float2 a13 = *(const float2*)(qp + (size_t)(g + 8) * (3 * C_EMB) + kt * 8 + 2 * t4);
            qa[kt][0] = __float_as_uint(a02.x * 0.25f);
            qa[kt][1] = __float_as_uint(a13.x * 0.25f);
            qa[kt][2] = __float_as_uint(a02.y * 0.25f);
            qa[kt][3] = __float_as_uint(a13.y * 0.25f);
        }
    }

    float o[2][4];
#pragma unroll
    for (int nt = 0; nt < 2; nt++)
#pragma unroll
        for (int i = 0; i < 4; i++) o[nt][i] = 0.f;
    float m0 = -1e30f, m1 = -1e30f, l0 = 0.f, l1 = 0.f;

    const int nch = qt + 1;
    prefetch(0);
    CP_COMMIT();

    for (int ci = 0; ci < nch; ci++) {
        const int k0 = ci * 64;
        const int st = ci & 1;
        CP_WAIT(0);
        __syncthreads();
        if (ci + 1 < nch) {
            prefetch(ci + 1);
            CP_COMMIT();
        }

        // scores S = Q @ K^T (16 x 64), tf32; K frags via float2 (permuted)
        float sf[8][4];
#pragma unroll
        for (int ns = 0; ns < 8; ns++) {
            sf[ns][0] = 0.f; sf[ns][1] = 0.f; sf[ns][2] = 0.f; sf[ns][3] = 0.f;
#pragma unroll
            for (int kt = 0; kt < 2; kt++) {
                float2 kf = *(const float2*)&Ks[st][ns * 8 + g][kt * 8 + 2 * t4];
                mma_tf32(sf[ns], qa[kt],
                         __float_as_uint(kf.x), __float_as_uint(kf.y));
            }
        }

        // causal mask (diagonal chunk only)
        if (ci == qt) {
            const int r0 = qbase + g, r1 = r0 + 8;
#pragma unroll
            for (int ns = 0; ns < 8; ns++) {
                int col = k0 + ns * 8 + 2 * t4;
                if (col     > r0) sf[ns][0] = -1e30f;
                if (col + 1 > r0) sf[ns][1] = -1e30f;
                if (col     > r1) sf[ns][2] = -1e30f;
                if (col + 1 > r1) sf[ns][3] = -1e30f;
            }
        }

        // row max over t4 lanes
        float rm0 = -1e30f, rm1 = -1e30f;
#pragma unroll
        for (int ns = 0; ns < 8; ns++) {
            rm0 = fmaxf(rm0, fmaxf(sf[ns][0], sf[ns][1]));
            rm1 = fmaxf(rm1, fmaxf(sf[ns][2], sf[ns][3]));
        }
        rm0 = fmaxf(rm0, __shfl_xor_sync(F, rm0, 1));
        rm0 = fmaxf(rm0, __shfl_xor_sync(F, rm0, 2));
        rm1 = fmaxf(rm1, __shfl_xor_sync(F, rm1, 1));
        rm1 = fmaxf(rm1, __shfl_xor_sync(F, rm1, 2));

        float nm0 = fmaxf(m0, rm0), nm1 = fmaxf(m1, rm1);
        float corr0 = __expf(m0 - nm0), corr1 = __expf(m1 - nm1);
        m0 = nm0; m1 = nm1;
        l0 *= corr0; l1 *= corr1;
#pragma unroll
        for (int nt = 0; nt < 2; nt++) {
            o[nt][0] *= corr0; o[nt][1] *= corr0;
            o[nt][2] *= corr1; o[nt][3] *= corr1;
        }

#pragma unroll
        for (int ns = 0; ns < 8; ns++) {
            sf[ns][0] = __expf(sf[ns][0] - m0);
            sf[ns][1] = __expf(sf[ns][1] - m0);
            sf[ns][2] = __expf(sf[ns][2] - m1);
            sf[ns][3] = __expf(sf[ns][3] - m1);
            l0 += sf[ns][0] + sf[ns][1];
            l1 += sf[ns][2] + sf[ns][3];
        }

        // O += P @ V with hi/lo bf16 splitting (3 terms; lo*lo dropped)
#pragma unroll
        for (int kt = 0; kt < 4; kt++) {
            uint32_t ph[4], pl[4];
#pragma unroll
            for (int r = 0; r < 4; r++) {
                const float a = sf[2 * kt + (r >> 1)][(r & 1) * 2    ];
                const float b = sf[2 * kt + (r >> 1)][(r & 1) * 2 + 1];
                uint32_t hp = pack_bf16x2(a, b);
                ph[r] = hp;
                float ha = u2f(hp << 16);
                float hb = u2f(hp & 0xffff0000u);
                pl[r] = pack_bf16x2(a - ha, b - hb);
            }
#pragma unroll
            for (int nt = 0; nt < 2; nt++) {
                uint32_t bh0 = *(const uint32_t*)&Vh[st][nt * 8 + g][kt * 16 + 2 * t4    ];
                uint32_t bh1 = *(const uint32_t*)&Vh[st][nt * 8 + g][kt * 16 + 8 + 2 * t4];
                uint32_t bl0 = *(const uint32_t*)&Vl[st][nt * 8 + g][kt * 16 + 2 * t4    ];
                uint32_t bl1 = *(const uint32_t*)&Vl[st][nt * 8 + g][kt * 16 + 8 + 2 * t4];
                mma_bf16(o[nt], ph, bh0, bh1);
                mma_bf16(o[nt], ph, bl0, bl1);
                mma_bf16(o[nt], pl, bh0, bh1);
            }
        }
    }

    l0 += __shfl_xor_sync(F, l0, 1);
    l0 += __shfl_xor_sync(F, l0, 2);
    l1 += __shfl_xor_sync(F, l1, 1);
    l1 += __shfl_xor_sync(F, l1, 2);
    const float inv0 = 1.f / l0, inv1 = 1.f / l1;

    // store O with within-8 channel permutation (proj GEMM reads permuted k)
    const int sp0 = sperm(2 * t4);
    const int sp1 = sperm(2 * t4 + 1);
    float* r0 = attn_out + (size_t)(qbase + g    ) * C_EMB + h * HDIM;
    float* r1 = attn_out + (size_t)(qbase + g + 8) * C_EMB + h * HDIM;
#pragma unroll
    for (int nt = 0; nt < 2; nt++) {
        r0[nt * 8 + sp0] = u2f(f2tf32(o[nt][0] * inv0));
        r0[nt * 8 + sp1] = u2f(f2tf32(o[nt][1] * inv0));
        r1[nt * 8 + sp0] = u2f(f2tf32(o[nt][2] * inv1));
        r1[nt * 8 + sp1] = u2f(f2tf32(o[nt][3] * inv1));
    }
}

// ---------------------------------------------------------------------------
// Launch
// ---------------------------------------------------------------------------
extern "C" void kernel_launch(void* const* d_in, const int* in_sizes, int n_in,
                              void* d_out, int out_size)
{
    const float* x     = (const float*)d_in[0];
    // d_in[1] = attn_mask (ignored; is_causal wins in the reference)
    const float* W_qkv = (const float*)d_in[2];
    const float* b_qkv = (const float*)d_in[3];
    const float* W_out = (const float*)d_in[4];
    const float* b_out = (const float*)d_in[5];
    float* out = (float*)d_out;

    float *qkv_buf, *attn_buf, *x_t, *wq_t, *wo_t;
    __nv_bfloat16 *vth_buf, *vtl_buf;
    cudaGetSymbolAddress((void**)&qkv_buf, g_qkv);
    cudaGetSymbolAddress((void**)&attn_buf, g_attn);
    cudaGetSymbolAddress((void**)&x_t, g_x);
    cudaGetSymbolAddress((void**)&wq_t, g_wqkv);
    cudaGetSymbolAddress((void**)&wo_t, g_wout);
    cudaGetSymbolAddress((void**)&vth_buf, g_vth);
    cudaGetSymbolAddress((void**)&vtl_buf, g_vtl);

    // 0) prologue: round+permute x; transpose+round+permute weights
    {
        int n8 = T_SEQ * C_EMB / 8;
        cvt_perm_kernel<<<(n8 + 255) / 256, 256>>>(x, x_t, n8);
        dim3 tb(32, 8);
        transpose_cvt_perm_kernel<<<dim3(3 * C_EMB / 32, C_EMB / 32), tb>>>(
            W_qkv, wq_t, C_EMB, 3 * C_EMB);
        transpose_cvt_perm_kernel<<<dim3(C_EMB / 32, C_EMB / 32), tb>>>(
            W_out, wo_t, C_EMB, C_EMB);
    }

    // 1) qkv = x @ W_qkv + b_qkv  (tf32-rounded; Q/K output channels permuted)
    {
        dim3 grid(3 * C_EMB / 128, T_SEQ / 128);
        gemm_tf32_bias_kernel<true, true><<<grid, 128>>>(
            x_t, wq_t, b_qkv, qkv_buf, T_SEQ, 3 * C_EMB, C_EMB);
    }

    // 1b) V -> hi/lo bf16 transposed [h][d][t]
    {
        dim3 grid(NHEADS, T_SEQ / 128);
        vt_kernel<<<grid, 128>>>(qkv_buf, vth_buf, vtl_buf);
    }

    // 2) causal attention (tf32-rounded, channels permuted)
    {
        dim3 grid(T_SEQ / 64, NHEADS);
        attn_tc_kernel<<<grid, 128>>>(qkv_buf, vth_buf, vtl_buf, attn_buf);
    }

    // 3) out = attn @ W_out + b_out (natural fp32 output)
    {
        dim3 grid(C_EMB / 128, T_SEQ / 128);
        gemm_tf32_bias_kernel<false, false><<<grid, 128>>>(
            attn_buf, wo_t, b_out, out, T_SEQ, C_EMB, C_EMB);
    }
}

// round 11
// speedup vs baseline: 1.3959x; 1.3959x over previous
#include <cuda_runtime.h>
#include <cuda_fp16.h>
#include <cstdint>
#include <cstddef>

#define T_SEQ   2048
#define C_EMB   1024
#define HDIM    16
#define NHEADS  64

// Scratch (no cudaMalloc allowed)
__device__ __half g_qkvh[T_SEQ * 2 * C_EMB];     // Q,K fp16 [t][2048]
__device__ float  g_v[T_SEQ * C_EMB];            // V fp32   [t][1024]
__device__ __half g_attnh[T_SEQ * C_EMB];        // attention out fp16
__device__ __half g_xh[T_SEQ * C_EMB];           // x fp16
__device__ __half g_wqkvh[3 * C_EMB * C_EMB];    // W_qkv^T fp16 [3072][1024]
__device__ __half g_wouth[C_EMB * C_EMB];        // W_out^T fp16 [1024][1024]
__device__ __half g_vth[NHEADS * HDIM * T_SEQ];  // V^T hi fp16 [h][d][t]
__device__ __half g_vtl[NHEADS * HDIM * T_SEQ];  // V^T lo fp16 [h][d][t]

__device__ __forceinline__ uint32_t pack_f16x2(float lo, float hi) {
    uint32_t d;
    asm("cvt.rn.f16x2.f32 %0, %1, %2;" : "=r"(d) : "f"(hi), "f"(lo));
    return d;
}

__device__ __forceinline__ void mma_fp16(float c[4], const uint32_t a[4],
                                         uint32_t b0, uint32_t b1) {
    asm volatile(
        "mma.sync.aligned.m16n8k16.row.col.f32.f16.f16.f32 "
        "{%0,%1,%2,%3}, {%4,%5,%6,%7}, {%8,%9}, {%0,%1,%2,%3};"
        : "+f"(c[0]), "+f"(c[1]), "+f"(c[2]), "+f"(c[3])
        : "r"(a[0]), "r"(a[1]), "r"(a[2]), "r"(a[3]), "r"(b0), "r"(b1));
}

#define CP_ASYNC16(dst, src) \
    asm volatile("cp.async.cg.shared.global [%0], [%1], 16;" :: "r"(dst), "l"(src))
#define CP_COMMIT() asm volatile("cp.async.commit_group;")
#define CP_WAIT(n)  asm volatile("cp.async.wait_group %0;" :: "n"(n))

// ---------------------------------------------------------------------------
// Prologue: fp32 -> fp16 elementwise (8 per thread)
// ---------------------------------------------------------------------------
__global__ void cvt_h_kernel(const float* __restrict__ in,
                             __half* __restrict__ out, int n8)
{
    int i = blockIdx.x * blockDim.x + threadIdx.x;
    if (i >= n8) return;
    float4 a = ((const float4*)in)[2 * i];
    float4 b = ((const float4*)in)[2 * i + 1];
    uint4 o;
    o.x = pack_f16x2(a.x, a.y);
    o.y = pack_f16x2(a.z, a.w);
    o.z = pack_f16x2(b.x, b.y);
    o.w = pack_f16x2(b.z, b.w);
    ((uint4*)out)[i] = o;
}

// Prologue: out[n][k] = fp16(in[k][n]); in is [R x Ccols] fp32, R = K dim.
__global__ void transpose_cvt_h_kernel(const float* __restrict__ in,
                                       __half* __restrict__ out, int R, int Ccols)
{
    __shared__ float t[32][33];
    const int bx = blockIdx.x * 32;   // n tile
    const int by = blockIdx.y * 32;   // k tile
    const int tx = threadIdx.x, ty = threadIdx.y;   // 32 x 8
#pragma unroll
    for (int j = 0; j < 4; j++) {
        int r = by + ty + j * 8;
        t[ty + j * 8][tx] = in[(size_t)r * Ccols + bx + tx];
    }
    __syncthreads();
#pragma unroll
    for (int j = 0; j < 4; j++) {
        int n = bx + ty + j * 8;
        out[(size_t)n * R + by + tx] = __float2half_rn(t[tx][ty + j * 8]);
    }
}

// ---------------------------------------------------------------------------
// V (fp32) -> hi/lo fp16 transposed [h][d][t]
// ---------------------------------------------------------------------------
__global__ void vt_kernel(const float* __restrict__ v,
                          __half* __restrict__ vth,
                          __half* __restrict__ vtl)
{
    __shared__ __half smh[16][132];
    __shared__ __half sml[16][132];
    const int h   = blockIdx.x;
    const int tt  = blockIdx.y;
    const int tid = threadIdx.x;
    const int token = tt * 128 + tid;

    const float* vp = v + (size_t)token * C_EMB + h * HDIM;
#pragma unroll
    for (int c = 0; c < 16; c++) {
        float val = vp[c];
        __half hh = __float2half_rn(val);
        float lo = val - __half2float(hh);
        smh[c][tid] = hh;
        sml[c][tid] = __float2half_rn(lo);
    }
    __syncthreads();

    const int d  = tid >> 3;
    const int c0 = (tid & 7) * 16;
    size_t base = ((size_t)(h * HDIM + d)) * T_SEQ + tt * 128 + c0;
    uint32_t* oh = (uint32_t*)(vth + base);
    uint32_t* ol = (uint32_t*)(vtl + base);
#pragma unroll
    for (int i = 0; i < 8; i++) {
        oh[i] = *(const uint32_t*)&smh[d][c0 + 2 * i];
        ol[i] = *(const uint32_t*)&sml[d][c0 + 2 * i];
    }
}

// ---------------------------------------------------------------------------
// FP16 GEMM (fp32 accum): C = A @ Bt^T + bias.
// A [M][K] fp16, Bt [N][K] fp16. 128x128 CTA, BK=16, 4 warps (64x64 tiles),
// m16n8k16 -> 32 MMAs / 32 LDS.32 per k-iter. 3-stage cp.async.
// MODE 0: fp32 out to Cf (stride N).
// MODE 1 (QKV): cols <2048 -> fp16 to Ch (stride 2048); cols >=2048 -> fp32
//               to Cf (stride 1024, col-2048).  Bias always fp32.
// ---------------------------------------------------------------------------
template <int MODE>
__global__ __launch_bounds__(128, 2) void gemm_fp16_bias_kernel(
    const __half* __restrict__ A, const __half* __restrict__ Bt,
    const float* __restrict__ bias, float* __restrict__ Cf,
    __half* __restrict__ Ch, int M, int N, int K)
{
    __shared__ __align__(16) __half As[3][128][24];
    __shared__ __align__(16) __half Bs[3][128][24];

    const int tid  = threadIdx.x;
    const int lane = tid & 31;
    const int warp = tid >> 5;
    const int wm   = (warp >> 1) * 64;
    const int wn   = (warp & 1) * 64;
    const int g    = lane >> 2;
    const int t4   = lane & 3;
    const int row0 = blockIdx.y * 128;
    const int col0 = blockIdx.x * 128;

    float acc[4][8][4];
#pragma unroll
    for (int ms = 0; ms < 4; ms++)
#pragma unroll
        for (int ns = 0; ns < 8; ns++)
#pragma unroll
            for (int i = 0; i < 4; i++) acc[ms][ns][i] = 0.f;

    auto issue_loads = [&](int k0, int st) {
#pragma unroll
        for (int it = 0; it < 2; it++) {
            int lin = tid + it * 128;           // 0..255
            int r   = lin >> 1;                 // 0..127
            int seg = (lin & 1) * 8;            // halves
            CP_ASYNC16((uint32_t)__cvta_generic_to_shared(&As[st][r][seg]),
                       A + (size_t)(row0 + r) * K + k0 + seg);
            CP_ASYNC16((uint32_t)__cvta_generic_to_shared(&Bs[st][r][seg]),
                       Bt + (size_t)(col0 + r) * K + k0 + seg);
        }
    };

    const int niter = K / 16;     // 64
    issue_loads(0, 0);
    CP_COMMIT();
    issue_loads(16, 1);
    CP_COMMIT();

    for (int i = 0; i < niter; i++) {
        if (i + 2 < niter) { CP_WAIT(1); } else { CP_WAIT(0); }
        __syncthreads();
        if (i + 2 < niter) {
            issue_loads((i + 2) * 16, (i + 2) % 3);
            CP_COMMIT();
        }
        const int st = i % 3;

        uint32_t af[4][4];
#pragma unroll
        for (int ms = 0; ms < 4; ms++) {
            af[ms][0] = *(const uint32_t*)&As[st][wm + ms * 16 + g    ][2 * t4    ];
            af[ms][1] = *(const uint32_t*)&As[st][wm + ms * 16 + g + 8][2 * t4    ];
            af[ms][2] = *(const uint32_t*)&As[st][wm + ms * 16 + g    ][2 * t4 + 8];
            af[ms][3] = *(const uint32_t*)&As[st][wm + ms * 16 + g + 8][2 * t4 + 8];
        }
        uint32_t bf[8][2];
#pragma unroll
        for (int ns = 0; ns < 8; ns++) {
            bf[ns][0] = *(const uint32_t*)&Bs[st][wn + ns * 8 + g][2 * t4    ];
            bf[ns][1] = *(const uint32_t*)&Bs[st][wn + ns * 8 + g][2 * t4 + 8];
        }
#pragma unroll
        for (int ms = 0; ms < 4; ms++)
#pragma unroll
            for (int ns = 0; ns < 8; ns++)
                mma_fp16(acc[ms][ns], af[ms], bf[ns][0], bf[ns][1]);
    }

#pragma unroll
    for (int ms = 0; ms < 4; ms++) {
#pragma unroll
        for (int ns = 0; ns < 8; ns++) {
            int r  = row0 + wm + ms * 16 + g;
            int cb = col0 + wn + ns * 8 + 2 * t4;
            float2 bv = *(const float2*)(bias + cb);
            float o00 = acc[ms][ns][0] + bv.x, o01 = acc[ms][ns][1] + bv.y;
            float o10 = acc[ms][ns][2] + bv.x, o11 = acc[ms][ns][3] + bv.y;
            if (MODE == 1) {
                if (col0 < 2048) {
                    *(uint32_t*)(Ch + (size_t)r * 2048 + cb) = pack_f16x2(o00, o01);
                    *(uint32_t*)(Ch + (size_t)(r + 8) * 2048 + cb) = pack_f16x2(o10, o11);
                } else {
                    float2 a, b;
                    a.x = o00; a.y = o01; b.x = o10; b.y = o11;
                    *(float2*)(Cf + (size_t)r * 1024 + cb - 2048) = a;
                    *(float2*)(Cf + (size_t)(r + 8) * 1024 + cb - 2048) = b;
                }
            } else {
                float2 a, b;
                a.x = o00; a.y = o01; b.x = o10; b.y = o11;
                *(float2*)(Cf + (size_t)r * N + cb) = a;
                *(float2*)(Cf + (size_t)(r + 8) * N + cb) = b;
            }
        }
    }
}

// ---------------------------------------------------------------------------
// Flash attention (causal), fp16 tensor cores throughout.
// Scores: m16n8k16 fp16 (Q,K fp16) -> 8 MMAs/chunk.
// PV: P fp16 (packed straight from score C-frags), V fp16 hi/lo -> 16 MMAs.
// Block: 1 head x 64 q-rows, 4 warps. 64-key chunks double-buffered.
// ---------------------------------------------------------------------------
__global__ __launch_bounds__(128) void attn_tc_kernel(
    const __half* __restrict__ qkvh,
    const __half* __restrict__ vth,
    const __half* __restrict__ vtl,
    __half* __restrict__ attnh)
{
    __shared__ __align__(16) __half Ks[2][64][24];
    __shared__ __align__(16) __half Vh[2][16][72];
    __shared__ __align__(16) __half Vl[2][16][72];

    const unsigned F = 0xffffffffu;
    const int h    = blockIdx.y;
    const int qt   = (int)gridDim.x - 1 - (int)blockIdx.x;  // heavy tiles first
    const int tid  = threadIdx.x;
    const int lane = tid & 31;
    const int w    = tid >> 5;
    const int g    = lane >> 2;
    const int t4   = lane & 3;
    const int qbase = qt * 64 + w * 16;

    const int krow = tid >> 1;          // 0..63
    const int kseg = (tid & 1) * 8;     // halves
    const int vdim = tid >> 3;          // 0..15
    const int vseg = (tid & 7) * 8;     // halves

    auto prefetch = [&](int ci) {
        const int st = ci & 1;
        const __half* kp = qkvh + (size_t)(ci * 64 + krow) * 2048
                           + 1024 + h * HDIM + kseg;
        CP_ASYNC16((uint32_t)__cvta_generic_to_shared(&Ks[st][krow][kseg]), kp);
        size_t vbase = (size_t)(h * HDIM + vdim) * T_SEQ + ci * 64 + vseg;
        CP_ASYNC16((uint32_t)__cvta_generic_to_shared(&Vh[st][vdim][vseg]), vth + vbase);
        CP_ASYNC16((uint32_t)__cvta_generic_to_shared(&Vl[st][vdim][vseg]), vtl + vbase);
    };

    // Q fragments, scaled by 0.25 (exact in fp16)
    uint32_t qa[4];
    {
        const __half* qp = qkvh + (size_t)qbase * 2048 + h * HDIM;
        qa[0] = *(const uint32_t*)(qp + (size_t)g       * 2048 + 2 * t4    );
        qa[1] = *(const uint32_t*)(qp + (size_t)(g + 8) * 2048 + 2 * t4    );
        qa[2] = *(const uint32_t*)(qp + (size_t)g       * 2048 + 2 * t4 + 8);
        qa[3] = *(const uint32_t*)(qp + (size_t)(g + 8) * 2048 + 2 * t4 + 8);
        const __half2 quarter = __float2half2_rn(0.25f);
#pragma unroll
        for (int i = 0; i < 4; i++) {
            __half2 q2 = *(__half2*)&qa[i];
            q2 = __hmul2(q2, quarter);
            qa[i] = *(uint32_t*)&q2;
        }
    }

    // O accumulators: o[nt][0,1] -> row g, o[nt][2,3] -> row g+8
    float o[2][4];
#pragma unroll
    for (int nt = 0; nt < 2; nt++)
#pragma unroll
        for (int i = 0; i < 4; i++) o[nt][i] = 0.f;
    float m0 = -1e30f, m1 = -1e30f, l0 = 0.f, l1 = 0.f;

    const int nch = qt + 1;
    prefetch(0);
    CP_COMMIT();

    for (int ci = 0; ci < nch; ci++) {
        const int k0 = ci * 64;
        const int st = ci & 1;
        CP_WAIT(0);
        __syncthreads();
        if (ci + 1 < nch) {
            prefetch(ci + 1);
            CP_COMMIT();
        }

        // scores S = Q @ K^T (16 x 64 per warp): one k16 MMA per ns
        float sf[8][4];
#pragma unroll
        for (int ns = 0; ns < 8; ns++) {
            sf[ns][0] = 0.f; sf[ns][1] = 0.f; sf[ns][2] = 0.f; sf[ns][3] = 0.f;
            uint32_t b0 = *(const uint32_t*)&Ks[st][ns * 8 + g][2 * t4    ];
            uint32_t b1 = *(const uint32_t*)&Ks[st][ns * 8 + g][2 * t4 + 8];
            mma_fp16(sf[ns], qa, b0, b1);
        }

        // causal mask (diagonal chunk only)
        if (ci == qt) {
            const int r0 = qbase + g, r1 = r0 + 8;
#pragma unroll
            for (int ns = 0; ns < 8; ns++) {
                int col = k0 + ns * 8 + 2 * t4;
                if (col     > r0) sf[ns][0] = -1e30f;
                if (col + 1 > r0) sf[ns][1] = -1e30f;
                if (col     > r1) sf[ns][2] = -1e30f;
                if (col + 1 > r1) sf[ns][3] = -1e30f;
            }
        }

        // row max over t4 lanes
        float rm0 = -1e30f, rm1 = -1e30f;
#pragma unroll
        for (int ns = 0; ns < 8; ns++) {
            rm0 = fmaxf(rm0, fmaxf(sf[ns][0], sf[ns][1]));
            rm1 = fmaxf(rm1, fmaxf(sf[ns][2], sf[ns][3]));
        }
        rm0 = fmaxf(rm0, __shfl_xor_sync(F, rm0, 1));
        rm0 = fmaxf(rm0, __shfl_xor_sync(F, rm0, 2));
        rm1 = fmaxf(rm1, __shfl_xor_sync(F, rm1, 1));
        rm1 = fmaxf(rm1, __shfl_xor_sync(F, rm1, 2));

        float nm0 = fmaxf(m0, rm0), nm1 = fmaxf(m1, rm1);
        float corr0 = __expf(m0 - nm0), corr1 = __expf(m1 - nm1);
        m0 = nm0; m1 = nm1;
        l0 *= corr0; l1 *= corr1;
#pragma unroll
        for (int nt = 0; nt < 2; nt++) {
            o[nt][0] *= corr0; o[nt][1] *= corr0;
            o[nt][2] *= corr1; o[nt][3] *= corr1;
        }

        // p = exp(s - m); accumulate l
#pragma unroll
        for (int ns = 0; ns < 8; ns++) {
            sf[ns][0] = __expf(sf[ns][0] - m0);
            sf[ns][1] = __expf(sf[ns][1] - m0);
            sf[ns][2] = __expf(sf[ns][2] - m1);
            sf[ns][3] = __expf(sf[ns][3] - m1);
            l0 += sf[ns][0] + sf[ns][1];
            l1 += sf[ns][2] + sf[ns][3];
        }

        // O += P @ V: P fp16 packed from score C-frags; V = Vh + Vl
#pragma unroll
        for (int kt = 0; kt < 4; kt++) {
            uint32_t pa[4];
            pa[0] = pack_f16x2(sf[2 * kt    ][0], sf[2 * kt    ][1]);
            pa[1] = pack_f16x2(sf[2 * kt    ][2], sf[2 * kt    ][3]);
            pa[2] = pack_f16x2(sf[2 * kt + 1][0], sf[2 * kt + 1][1]);
            pa[3] = pack_f16x2(sf[2 * kt + 1][2], sf[2 * kt + 1][3]);
#pragma unroll
            for (int nt = 0; nt < 2; nt++) {
                uint32_t bh0 = *(const uint32_t*)&Vh[st][nt * 8 + g][kt * 16 + 2 * t4    ];
                uint32_t bh1 = *(const uint32_t*)&Vh[st][nt * 8 + g][kt * 16 + 8 + 2 * t4];
                uint32_t bl0 = *(const uint32_t*)&Vl[st][nt * 8 + g][kt * 16 + 2 * t4    ];
                uint32_t bl1 = *(const uint32_t*)&Vl[st][nt * 8 + g][kt * 16 + 8 + 2 * t4];
                mma_fp16(o[nt], pa, bh0, bh1);
                mma_fp16(o[nt], pa, bl0, bl1);
            }
        }
    }

    // reduce l over t4 lanes; rows g / g+8 use l0 / l1
    l0 += __shfl_xor_sync(F, l0, 1);
    l0 += __shfl_xor_sync(F, l0, 2);
    l1 += __shfl_xor_sync(F, l1, 1);
    l1 += __shfl_xor_sync(F, l1, 2);
    const float inv0 = 1.f / l0, inv1 = 1.f / l1;

    // store O as fp16 (proj GEMM operand)
    __half* r0 = attnh + (size_t)(qbase + g    ) * C_EMB + h * HDIM;
    __half* r1 = attnh + (size_t)(qbase + g + 8) * C_EMB + h * HDIM;
#pragma unroll
    for (int nt = 0; nt < 2; nt++) {
        *(uint32_t*)(r0 + nt * 8 + 2 * t4) =
            pack_f16x2(o[nt][0] * inv0, o[nt][1] * inv0);
        *(uint32_t*)(r1 + nt * 8 + 2 * t4) =
            pack_f16x2(o[nt][2] * inv1, o[nt][3] * inv1);
    }
}

// ---------------------------------------------------------------------------
// Launch
// ---------------------------------------------------------------------------
extern "C" void kernel_launch(void* const* d_in, const int* in_sizes, int n_in,
                              void* d_out, int out_size)
{
    const float* x     = (const float*)d_in[0];
    // d_in[1] = attn_mask (ignored; is_causal wins in the reference)
    const float* W_qkv = (const float*)d_in[2];
    const float* b_qkv = (const float*)d_in[3];
    const float* W_out = (const float*)d_in[4];
    const float* b_out = (const float*)d_in[5];
    float* out = (float*)d_out;

    __half *qkvh, *attnh, *xh, *wqh, *woh, *vth, *vtl;
    float *vbuf;
    cudaGetSymbolAddress((void**)&qkvh, g_qkvh);
    cudaGetSymbolAddress((void**)&vbuf, g_v);
    cudaGetSymbolAddress((void**)&attnh, g_attnh);
    cudaGetSymbolAddress((void**)&xh, g_xh);
    cudaGetSymbolAddress((void**)&wqh, g_wqkvh);
    cudaGetSymbolAddress((void**)&woh, g_wouth);
    cudaGetSymbolAddress((void**)&vth, g_vth);
    cudaGetSymbolAddress((void**)&vtl, g_vtl);

    // 0) prologue: x -> fp16; weights -> transposed fp16
    {
        int n8 = T_SEQ * C_EMB / 8;
        cvt_h_kernel<<<(n8 + 255) / 256, 256>>>(x, xh, n8);
        dim3 tb(32, 8);
        transpose_cvt_h_kernel<<<dim3(3 * C_EMB / 32, C_EMB / 32), tb>>>(
            W_qkv, wqh, C_EMB, 3 * C_EMB);
        transpose_cvt_h_kernel<<<dim3(C_EMB / 32, C_EMB / 32), tb>>>(
            W_out, woh, C_EMB, C_EMB);
    }

    // 1) qkv = x @ W_qkv + b_qkv   (Q,K fp16 out; V fp32 out)
    {
        dim3 grid(3 * C_EMB / 128, T_SEQ / 128);
        gemm_fp16_bias_kernel<1><<<grid, 128>>>(
            xh, wqh, b_qkv, vbuf, qkvh, T_SEQ, 3 * C_EMB, C_EMB);
    }

    // 1b) V -> hi/lo fp16 transposed [h][d][t]
    {
        dim3 grid(NHEADS, T_SEQ / 128);
        vt_kernel<<<grid, 128>>>(vbuf, vth, vtl);
    }

    // 2) causal attention (fp16 out)
    {
        dim3 grid(T_SEQ / 64, NHEADS);
        attn_tc_kernel<<<grid, 128>>>(qkvh, vth, vtl, attnh);
    }

    // 3) out = attn @ W_out + b_out (fp32 out)
    {
        dim3 grid(C_EMB / 128, T_SEQ / 128);
        gemm_fp16_bias_kernel<0><<<grid, 128>>>(
            attnh, woh, b_out, out, (__half*)0, T_SEQ, C_EMB, C_EMB);
    }
}